// round 5
// baseline (speedup 1.0000x reference)
#include <cuda_runtime.h>
#include <cuda_bf16.h>

// DiagPooling: x [B=8, C=128, H=512, W=512] fp32 -> out [B, 1, 513] fp32
// out[b, 0, o] = (1 / (128 * (512 - |o-256|))) * sum_{c,i} x[b, c, i, i + o - 256]
//
// Flat uniform vector decomposition (validated in R4):
//   Pair row p (p<256, cols [0, p+256], aligned start) with row p+256
//   (cols [p, 511], start aligned DOWN to p&~3). float4 slot counts:
//   nvec1 = (p>>2)+65 and nvec2 = 128-(p>>2) -> sum EXACTLY 193 for all p.
// Channel split x4 (32 channels per thread-item):
//   total thread-items = 8 * 256 * 4 * 193 = 1,581,056 = 6176 blocks x 256.
//   Every lane active, every block identical -> max parallelism + LDG.128.
// Each c-slice accumulates RAW sums into its own scratch slice (no
// cross-slice contention; per-address serialization same as R1).
// Epilogue kernel: out = (sum of 4 slices) / denom, then re-zeros scratch
// so the next graph replay starts clean (scratch is statically zeroed for
// the very first call). Every call performs identical work.

#define B_DIM 8
#define C_DIM 128
#define H_DIM 512
#define W_DIM 512
#define N_OFF 513
#define OUT_ELEMS (B_DIM * N_OFF)       // 4104

#define C_SLICES 4
#define C_PER_SLICE (C_DIM / C_SLICES)  // 32
#define SLOTS_PER_PAIR 193
// item id g = (((b*256 + p)*4 + cs)*193 + s)
#define TOTAL_ITEMS (B_DIM * 256 * C_SLICES * SLOTS_PER_PAIR)  // 1581056
#define NBLOCKS (TOTAL_ITEMS / 256)                            // 6176

__device__ float g_scratch[C_SLICES * OUT_ELEMS];   // zero-initialized at load

__global__ __launch_bounds__(256, 8) void diag_pool_kernel(
    const float* __restrict__ x)
{
    const int g = blockIdx.x * 256 + threadIdx.x;

    // decode (b, p, cs, s)
    const int s  = g % SLOTS_PER_PAIR;
    const int q1 = g / SLOTS_PER_PAIR;
    const int cs = q1 & 3;
    const int q2 = q1 >> 2;
    const int p  = q2 & 255;
    const int b  = q2 >> 8;

    const int nvec1 = (p >> 2) + 65;

    int i, jbase;
    if (s < nvec1) {                      // row p, cols [0, p+256]
        i = p;
        jbase = 4 * s;
    } else {                              // row p+256, cols [p, 511]
        i = p + 256;
        jbase = (p & ~3) + 4 * (s - nvec1);
    }

    const size_t S = (size_t)H_DIM * W_DIM;     // channel stride
    const float* ptr = x + ((size_t)b * C_DIM + (size_t)cs * C_PER_SLICE) * S
                         + (size_t)i * W_DIM + jbase;

    float ax0 = 0.f, ay0 = 0.f, az0 = 0.f, aw0 = 0.f;
    float ax1 = 0.f, ay1 = 0.f, az1 = 0.f, aw1 = 0.f;

    #pragma unroll 8
    for (int c = 0; c < C_PER_SLICE; c += 2) {
        const float4 v0 = __ldg((const float4*)(ptr + (size_t)(c + 0) * S));
        const float4 v1 = __ldg((const float4*)(ptr + (size_t)(c + 1) * S));
        ax0 += v0.x; ay0 += v0.y; az0 += v0.z; aw0 += v0.w;
        ax1 += v1.x; ay1 += v1.y; az1 += v1.z; aw1 += v1.w;
    }

    float sum[4];
    sum[0] = ax0 + ax1;
    sum[1] = ay0 + ay1;
    sum[2] = az0 + az1;
    sum[3] = aw0 + aw1;

    // valid column window for this row
    const int jlo = (i >= 256) ? (i - 256) : 0;
    const int jhi = (i <= 255) ? (i + 256) : (H_DIM - 1);

    float* dst = g_scratch + cs * OUT_ELEMS + b * N_OFF;

    #pragma unroll
    for (int k = 0; k < 4; k++) {
        const int j = jbase + k;
        if (j >= jlo && j <= jhi) {
            const int o = j - i + 256;    // diagonal id 0..512
            atomicAdd(dst + o, sum[k]);   // raw sum, scaled in epilogue
        }
    }
}

__global__ void reduce_kernel(float* __restrict__ out)
{
    const int idx = blockIdx.x * blockDim.x + threadIdx.x;
    if (idx >= OUT_ELEMS) return;

    const int o = idx % N_OFF;

    float v = 0.f;
    #pragma unroll
    for (int cs = 0; cs < C_SLICES; cs++) {
        v += g_scratch[cs * OUT_ELEMS + idx];
        g_scratch[cs * OUT_ELEMS + idx] = 0.f;   // clean for next replay
    }

    const int off  = o - 256;
    const int dlen = H_DIM - (off < 0 ? -off : off);
    out[idx] = v / ((float)C_DIM * (float)dlen);
}

extern "C" void kernel_launch(void* const* d_in, const int* in_sizes, int n_in,
                              void* d_out, int out_size) {
    const float* x = (const float*)d_in[0];
    float* out = (float*)d_out;

    diag_pool_kernel<<<NBLOCKS, 256>>>(x);
    reduce_kernel<<<(OUT_ELEMS + 255) / 256, 256>>>(out);
}